// round 3
// baseline (speedup 1.0000x reference)
#include <cuda_runtime.h>
#include <cstdint>

// LIF spike scan over T=8 (contiguous innermost axis).
// x: [32,128,32,32,8] fp32 -> spikes {0,1} fp32, same shape.
// Persistent grid-stride kernel: 1184 CTAs (148 SMs x 8), each thread processes
// 4 positions per loop iteration with 4 independent 256-bit loads (MLP=4).

#define TAU 0.2f
#define VTH 0.3f

__device__ __forceinline__ void lif_scan8(const float* __restrict__ xp,
                                          float* __restrict__ op,
                                          float x0, float x1, float x2, float x3,
                                          float x4, float x5, float x6, float x7) {
    float u, o;
    float s0, s1, s2, s3, s4, s5, s6, s7;
    u = x0;                        o = (u > VTH) ? 1.0f : 0.0f; s0 = o;
    u = TAU * u * (1.0f - o) + x1; o = (u > VTH) ? 1.0f : 0.0f; s1 = o;
    u = TAU * u * (1.0f - o) + x2; o = (u > VTH) ? 1.0f : 0.0f; s2 = o;
    u = TAU * u * (1.0f - o) + x3; o = (u > VTH) ? 1.0f : 0.0f; s3 = o;
    u = TAU * u * (1.0f - o) + x4; o = (u > VTH) ? 1.0f : 0.0f; s4 = o;
    u = TAU * u * (1.0f - o) + x5; o = (u > VTH) ? 1.0f : 0.0f; s5 = o;
    u = TAU * u * (1.0f - o) + x6; o = (u > VTH) ? 1.0f : 0.0f; s6 = o;
    u = TAU * u * (1.0f - o) + x7; o = (u > VTH) ? 1.0f : 0.0f; s7 = o;
    asm volatile(
        "st.global.cs.v8.f32 [%0], {%1,%2,%3,%4,%5,%6,%7,%8};"
        :: "l"(op), "f"(s0), "f"(s1), "f"(s2), "f"(s3),
           "f"(s4), "f"(s5), "f"(s6), "f"(s7) : "memory");
}

#define LDG256(dst0,dst1,dst2,dst3,dst4,dst5,dst6,dst7, ptr) \
    asm volatile("ld.global.cs.v8.f32 {%0,%1,%2,%3,%4,%5,%6,%7}, [%8];" \
        : "=f"(dst0), "=f"(dst1), "=f"(dst2), "=f"(dst3), \
          "=f"(dst4), "=f"(dst5), "=f"(dst6), "=f"(dst7) : "l"(ptr))

__global__ void __launch_bounds__(256, 8)
lif_spike_kernel(const float* __restrict__ x, float* __restrict__ out, int n_pos) {
    const int nthreads = gridDim.x * blockDim.x;
    int p = blockIdx.x * blockDim.x + threadIdx.x;

    // Main loop: 4 positions per iteration, 4 independent 256-bit loads up front.
    for (; p + 3 * nthreads < n_pos; p += 4 * nthreads) {
        const float* xp0 = x + (size_t)p * 8;
        const float* xp1 = x + ((size_t)p + nthreads) * 8;
        const float* xp2 = x + ((size_t)p + 2 * (size_t)nthreads) * 8;
        const float* xp3 = x + ((size_t)p + 3 * (size_t)nthreads) * 8;

        float a0,a1,a2,a3,a4,a5,a6,a7;
        float b0,b1,b2,b3,b4,b5,b6,b7;
        float c0,c1,c2,c3,c4,c5,c6,c7;
        float d0,d1,d2,d3,d4,d5,d6,d7;
        LDG256(a0,a1,a2,a3,a4,a5,a6,a7, xp0);
        LDG256(b0,b1,b2,b3,b4,b5,b6,b7, xp1);
        LDG256(c0,c1,c2,c3,c4,c5,c6,c7, xp2);
        LDG256(d0,d1,d2,d3,d4,d5,d6,d7, xp3);

        lif_scan8(xp0, out + (size_t)p * 8,                         a0,a1,a2,a3,a4,a5,a6,a7);
        lif_scan8(xp1, out + ((size_t)p + nthreads) * 8,            b0,b1,b2,b3,b4,b5,b6,b7);
        lif_scan8(xp2, out + ((size_t)p + 2*(size_t)nthreads) * 8,  c0,c1,c2,c3,c4,c5,c6,c7);
        lif_scan8(xp3, out + ((size_t)p + 3*(size_t)nthreads) * 8,  d0,d1,d2,d3,d4,d5,d6,d7);
    }

    // Tail: remaining positions one at a time.
    for (; p < n_pos; p += nthreads) {
        const float* xp = x + (size_t)p * 8;
        float a0,a1,a2,a3,a4,a5,a6,a7;
        LDG256(a0,a1,a2,a3,a4,a5,a6,a7, xp);
        lif_scan8(xp, out + (size_t)p * 8, a0,a1,a2,a3,a4,a5,a6,a7);
    }
}

extern "C" void kernel_launch(void* const* d_in, const int* in_sizes, int n_in,
                              void* d_out, int out_size) {
    const float* x = (const float*)d_in[0];
    float* out = (float*)d_out;
    int n_total = in_sizes[0];   // B*C*H*W*T
    int n_pos = n_total / 8;

    // Persistent: 148 SMs * 8 CTAs/SM (regs<=32 at 256 thr => occupancy 8 fine)
    int threads = 256;
    int blocks = 148 * 8;
    lif_spike_kernel<<<blocks, threads>>>(x, out, n_pos);
}

// round 4
// speedup vs baseline: 1.3286x; 1.3286x over previous
#include <cuda_runtime.h>
#include <cstdint>

// LIF spike scan over T=8 (contiguous innermost axis).
// x: [32,128,32,32,8] fp32 -> spikes {0,1} fp32, same shape.
// Flat launch (no loop — CTA replacement provides the memory pipelining).
// Each thread handles 2 positions (block-local stride 256): 2 independent
// 256-bit loads up front (MLP=2), 2 scans, 2 stores.

#define TAU 0.2f
#define VTH 0.3f

#define LDG256(d0,d1,d2,d3,d4,d5,d6,d7, ptr) \
    asm volatile("ld.global.cs.v8.f32 {%0,%1,%2,%3,%4,%5,%6,%7}, [%8];" \
        : "=f"(d0), "=f"(d1), "=f"(d2), "=f"(d3), \
          "=f"(d4), "=f"(d5), "=f"(d6), "=f"(d7) : "l"(ptr))

#define STG256(ptr, s0,s1,s2,s3,s4,s5,s6,s7) \
    asm volatile("st.global.cs.v8.f32 [%0], {%1,%2,%3,%4,%5,%6,%7,%8};" \
        :: "l"(ptr), "f"(s0), "f"(s1), "f"(s2), "f"(s3), \
           "f"(s4), "f"(s5), "f"(s6), "f"(s7) : "memory")

__device__ __forceinline__ void lif8(float x0, float x1, float x2, float x3,
                                     float x4, float x5, float x6, float x7,
                                     float& s0, float& s1, float& s2, float& s3,
                                     float& s4, float& s5, float& s6, float& s7) {
    float u, o;
    u = x0;                        o = (u > VTH) ? 1.0f : 0.0f; s0 = o;
    u = TAU * u * (1.0f - o) + x1; o = (u > VTH) ? 1.0f : 0.0f; s1 = o;
    u = TAU * u * (1.0f - o) + x2; o = (u > VTH) ? 1.0f : 0.0f; s2 = o;
    u = TAU * u * (1.0f - o) + x3; o = (u > VTH) ? 1.0f : 0.0f; s3 = o;
    u = TAU * u * (1.0f - o) + x4; o = (u > VTH) ? 1.0f : 0.0f; s4 = o;
    u = TAU * u * (1.0f - o) + x5; o = (u > VTH) ? 1.0f : 0.0f; s5 = o;
    u = TAU * u * (1.0f - o) + x6; o = (u > VTH) ? 1.0f : 0.0f; s6 = o;
    u = TAU * u * (1.0f - o) + x7; o = (u > VTH) ? 1.0f : 0.0f; s7 = o;
}

__global__ void __launch_bounds__(256, 8)
lif_spike_kernel(const float* __restrict__ x, float* __restrict__ out, int n_pos) {
    // Each CTA covers 512 consecutive positions: thread t -> base+t and base+256+t.
    int base = blockIdx.x * 512;
    int p0 = base + threadIdx.x;
    int p1 = p0 + 256;

    const float* xp0 = x + (size_t)p0 * 8;
    const float* xp1 = x + (size_t)p1 * 8;

    float a0,a1,a2,a3,a4,a5,a6,a7;
    float b0,b1,b2,b3,b4,b5,b6,b7;

    bool v0 = (p0 < n_pos);
    bool v1 = (p1 < n_pos);

    if (v0) LDG256(a0,a1,a2,a3,a4,a5,a6,a7, xp0);
    if (v1) LDG256(b0,b1,b2,b3,b4,b5,b6,b7, xp1);

    if (v0) {
        float s0,s1,s2,s3,s4,s5,s6,s7;
        lif8(a0,a1,a2,a3,a4,a5,a6,a7, s0,s1,s2,s3,s4,s5,s6,s7);
        STG256(out + (size_t)p0 * 8, s0,s1,s2,s3,s4,s5,s6,s7);
    }
    if (v1) {
        float s0,s1,s2,s3,s4,s5,s6,s7;
        lif8(b0,b1,b2,b3,b4,b5,b6,b7, s0,s1,s2,s3,s4,s5,s6,s7);
        STG256(out + (size_t)p1 * 8, s0,s1,s2,s3,s4,s5,s6,s7);
    }
}

extern "C" void kernel_launch(void* const* d_in, const int* in_sizes, int n_in,
                              void* d_out, int out_size) {
    const float* x = (const float*)d_in[0];
    float* out = (float*)d_out;
    int n_total = in_sizes[0];   // B*C*H*W*T
    int n_pos = n_total / 8;

    int threads = 256;
    int blocks = (n_pos + 511) / 512;   // 2 positions per thread
    lif_spike_kernel<<<blocks, threads>>>(x, out, n_pos);
}

// round 5
// speedup vs baseline: 1.3765x; 1.0360x over previous
#include <cuda_runtime.h>
#include <cstdint>

// LIF spike scan over T=8 (contiguous innermost axis).
// x: [32,128,32,32,8] fp32 -> spikes {0,1} fp32, same shape.
// Flat launch, 1 position per thread, 256-bit ld/st.
// Load: .cs (read-once, evict-first — zero reuse stream).
// Store: default .wb (let dirty output lines sit in L2 and drain lazily,
//        instead of .cs forcing early writeback that fights the read stream).

#define TAU 0.2f
#define VTH 0.3f

__global__ void __launch_bounds__(256, 8)
lif_spike_kernel(const float* __restrict__ x, float* __restrict__ out, int n_pos) {
    int p = blockIdx.x * blockDim.x + threadIdx.x;
    if (p >= n_pos) return;

    const float* xp = x + (size_t)p * 8;
    float* op = out + (size_t)p * 8;

    float x0, x1, x2, x3, x4, x5, x6, x7;
    asm volatile(
        "ld.global.cs.v8.f32 {%0,%1,%2,%3,%4,%5,%6,%7}, [%8];"
        : "=f"(x0), "=f"(x1), "=f"(x2), "=f"(x3),
          "=f"(x4), "=f"(x5), "=f"(x6), "=f"(x7)
        : "l"(xp));

    float u, o;
    float s0, s1, s2, s3, s4, s5, s6, s7;
    u = x0;                        o = (u > VTH) ? 1.0f : 0.0f; s0 = o;
    u = TAU * u * (1.0f - o) + x1; o = (u > VTH) ? 1.0f : 0.0f; s1 = o;
    u = TAU * u * (1.0f - o) + x2; o = (u > VTH) ? 1.0f : 0.0f; s2 = o;
    u = TAU * u * (1.0f - o) + x3; o = (u > VTH) ? 1.0f : 0.0f; s3 = o;
    u = TAU * u * (1.0f - o) + x4; o = (u > VTH) ? 1.0f : 0.0f; s4 = o;
    u = TAU * u * (1.0f - o) + x5; o = (u > VTH) ? 1.0f : 0.0f; s5 = o;
    u = TAU * u * (1.0f - o) + x6; o = (u > VTH) ? 1.0f : 0.0f; s6 = o;
    u = TAU * u * (1.0f - o) + x7; o = (u > VTH) ? 1.0f : 0.0f; s7 = o;

    asm volatile(
        "st.global.v8.f32 [%0], {%1,%2,%3,%4,%5,%6,%7,%8};"
        :
        : "l"(op),
          "f"(s0), "f"(s1), "f"(s2), "f"(s3),
          "f"(s4), "f"(s5), "f"(s6), "f"(s7)
        : "memory");
}

extern "C" void kernel_launch(void* const* d_in, const int* in_sizes, int n_in,
                              void* d_out, int out_size) {
    const float* x = (const float*)d_in[0];
    float* out = (float*)d_out;
    int n_total = in_sizes[0];   // B*C*H*W*T
    int n_pos = n_total / 8;

    int threads = 256;
    int blocks = (n_pos + threads - 1) / threads;
    lif_spike_kernel<<<blocks, threads>>>(x, out, n_pos);
}